// round 10
// baseline (speedup 1.0000x reference)
#include <cuda_runtime.h>
#include <cstdint>

#define M_PTS 5151
#define HIDN  256
#define BB    16
#define SS    256
#define TT    1024
#define GRID_N 101
#define TDIM   16
#define NTILES 28
#define TC     32
#define TSTR   36
#define CUT 0.018f

#define OFF_BOUT 0
#define OFF_D    16384
#define OFF_M    (OFF_D + BB*M_PTS)
#define OFF_IS   (OFF_M + BB*TT)
#define OFF_MESH (OFF_IS + BB*M_PTS)

// ---------------- scratch ----------------
__device__ float g_y[5248*HIDN];                 // fp32 output of last layer
__device__ float g_xhi[5248*HIDN];
__device__ float g_xlo[5248*HIDN];
__device__ float g_yhi[5248*HIDN];
__device__ float g_ylo[5248*HIDN];
__device__ float g_whi[3*HIDN*HIDN];
__device__ float g_wlo[3*HIDN*HIDN];
__device__ float g_density[M_PTS];
__device__ float g_cwc[BB*HIDN];
__device__ float g_init[BB*M_PTS];
__device__ float g_bpart[BB*NTILES*TT];

__device__ __forceinline__ float fast_tanh(float x) {
    float r;
    asm("tanh.approx.f32 %0, %1;" : "=f"(r) : "f"(x));
    return r;
}

__device__ __forceinline__ float to_tf32(float x) {
    uint32_t r;
    asm("cvt.rna.tf32.f32 %0, %1;" : "=r"(r) : "f"(x));
    return __uint_as_float(r);
}

__device__ __forceinline__ void mma_tf32(float* c, const float* a, const float* b) {
    asm volatile(
        "mma.sync.aligned.m16n8k8.row.col.f32.tf32.tf32.f32 "
        "{%0,%1,%2,%3}, {%4,%5,%6,%7}, {%8,%9}, {%0,%1,%2,%3};"
        : "+f"(c[0]), "+f"(c[1]), "+f"(c[2]), "+f"(c[3])
        : "r"(__float_as_uint(a[0])), "r"(__float_as_uint(a[1])),
          "r"(__float_as_uint(a[2])), "r"(__float_as_uint(a[3])),
          "r"(__float_as_uint(b[0])), "r"(__float_as_uint(b[1])));
}

// ---------------- W split (once) ----------------
__global__ void k_wsplit(const float* __restrict__ Wr) {
    int i = blockIdx.x*256 + threadIdx.x;
    if (i >= 3*HIDN*HIDN) return;
    float w = Wr[i];
    float hi = to_tf32(w);
    g_whi[i] = hi;
    g_wlo[i] = to_tf32(w - hi);
}

// ---------------- density input layer ----------------
__global__ void k_dens_in(const float* __restrict__ mesh,
                          const float* __restrict__ Win,
                          const float* __restrict__ bin) {
    int m = blockIdx.x;
    int j = threadIdx.x;
    float be = mesh[2*m], al = mesh[2*m+1];
    float v = fmaxf(be*Win[j] + al*Win[HIDN+j] + bin[j], 0.f);
    float hi = to_tf32(v);
    g_xhi[m*HIDN + j] = hi;
    g_xlo[m*HIDN + j] = to_tf32(v - hi);
}

// ---------------- residual layer via 3xTF32 mma ----------------
// 128x64 tile, 256 thr, 8 warps (warp = 32 rows x 32 cols), BK=16.
// Grid 41x4 = 164 blocks -> ~one wave at 2 blocks/SM.
__global__ void __launch_bounds__(256) k_res_tc(const float* __restrict__ bias,
                                                int flip, int layer, int last) {
    const float* Xhi = flip ? g_yhi : g_xhi;
    const float* Xlo = flip ? g_ylo : g_xlo;
    float* Yhi = flip ? g_xhi : g_yhi;
    float* Ylo = flip ? g_xlo : g_ylo;
    const float* Whi = g_whi + layer*HIDN*HIDN;
    const float* Wlo = g_wlo + layer*HIDN*HIDN;

    __shared__ __align__(16) float Ah[128][20];
    __shared__ __align__(16) float Al[128][20];
    __shared__ __align__(16) float Bh[16][72];
    __shared__ __align__(16) float Bl[16][72];

    int bm = blockIdx.x*128, bn = blockIdx.y*64;
    int tid = threadIdx.x;
    int warp = tid >> 5, lane = tid & 31;
    int lr = lane >> 2, lc = lane & 3;
    int m_base = (warp >> 1) * 32;     // 4 m-groups of 32 rows
    int n_base = (warp & 1) * 32;      // 2 n-groups of 32 cols

    float acc[2][4][4];
#pragma unroll
    for (int t = 0; t < 2; t++)
#pragma unroll
        for (int j = 0; j < 4; j++)
#pragma unroll
            for (int q = 0; q < 4; q++) acc[t][j][q] = 0.f;

    const float4 z4 = make_float4(0.f,0.f,0.f,0.f);

    // A staging: 128 rows x 16 k = 512 float4 per array; 2/thread
    int ar[2]; int ac4 = (tid & 3) * 4;
    ar[0] = tid >> 2; ar[1] = (tid >> 2) + 64;
    // B staging: 16 k x 64 n = 256 float4 per array; 1/thread
    int bkr = tid >> 4;               // 0..15
    int bc4 = (tid & 15) * 4;

    for (int k0 = 0; k0 < HIDN; k0 += 16) {
#pragma unroll
        for (int u = 0; u < 2; u++) {
            int gr = bm + ar[u];
            bool ok = gr < M_PTS;
            size_t g = (size_t)(ok ? gr : 0)*HIDN + k0 + ac4;
            *(float4*)&Ah[ar[u]][ac4] = ok ? *(const float4*)&Xhi[g] : z4;
            *(float4*)&Al[ar[u]][ac4] = ok ? *(const float4*)&Xlo[g] : z4;
        }
        {
            size_t g = (size_t)(k0 + bkr)*HIDN + bn + bc4;
            *(float4*)&Bh[bkr][bc4] = *(const float4*)&Whi[g];
            *(float4*)&Bl[bkr][bc4] = *(const float4*)&Wlo[g];
        }
        __syncthreads();

#pragma unroll
        for (int kk = 0; kk < 16; kk += 8) {
            float ah[2][4], al[2][4];
#pragma unroll
            for (int t = 0; t < 2; t++) {
                int r = m_base + t*16 + lr;
                ah[t][0] = Ah[r    ][kk + lc];
                ah[t][1] = Ah[r + 8][kk + lc];
                ah[t][2] = Ah[r    ][kk + lc + 4];
                ah[t][3] = Ah[r + 8][kk + lc + 4];
                al[t][0] = Al[r    ][kk + lc];
                al[t][1] = Al[r + 8][kk + lc];
                al[t][2] = Al[r    ][kk + lc + 4];
                al[t][3] = Al[r + 8][kk + lc + 4];
            }
            float bh[4][2], bl[4][2];
#pragma unroll
            for (int j = 0; j < 4; j++) {
                int n = n_base + j*8 + lr;
                bh[j][0] = Bh[kk + lc    ][n];
                bh[j][1] = Bh[kk + lc + 4][n];
                bl[j][0] = Bl[kk + lc    ][n];
                bl[j][1] = Bl[kk + lc + 4][n];
            }
#pragma unroll
            for (int t = 0; t < 2; t++)
#pragma unroll
                for (int j = 0; j < 4; j++) {
                    mma_tf32(acc[t][j], ah[t], bh[j]);
                    mma_tf32(acc[t][j], ah[t], bl[j]);
                    mma_tf32(acc[t][j], al[t], bh[j]);
                }
        }
        __syncthreads();
    }

    // epilogue: y = (xhi+xlo) + relu(acc + bias); emit tf32 split of y
#pragma unroll
    for (int t = 0; t < 2; t++) {
        int r0 = bm + m_base + t*16 + lr;
        int r1 = r0 + 8;
#pragma unroll
        for (int j = 0; j < 4; j++) {
            int c = bn + n_base + j*8 + 2*lc;
            float2 bz = *(const float2*)&bias[c];
#pragma unroll
            for (int h = 0; h < 2; h++) {
                int r = h ? r1 : r0;
                if (r >= M_PTS) continue;
                float v0 = acc[t][j][h*2 + 0] + bz.x;
                float v1 = acc[t][j][h*2 + 1] + bz.y;
                size_t g = (size_t)r*HIDN + c;
                float2 xh = *(const float2*)&Xhi[g];
                float2 xl = *(const float2*)&Xlo[g];
                float y0 = (xh.x + xl.x) + fmaxf(v0, 0.f);
                float y1 = (xh.y + xl.y) + fmaxf(v1, 0.f);
                float h0 = to_tf32(y0), h1 = to_tf32(y1);
                *(float2*)&Yhi[g] = make_float2(h0, h1);
                *(float2*)&Ylo[g] = make_float2(to_tf32(y0 - h0), to_tf32(y1 - h1));
                if (last)
                    *(float2*)&g_y[g] = make_float2(y0, y1);
            }
        }
    }
}

// ---------------- density output ----------------
__global__ void k_dens_out(const float* __restrict__ Wout,
                           const float* __restrict__ bout) {
    int w = blockIdx.x*8 + (threadIdx.x >> 5);
    int lane = threadIdx.x & 31;
    if (w >= M_PTS) return;
    float acc = 0.f;
#pragma unroll
    for (int i = 0; i < 8; i++)
        acc += g_y[w*HIDN + lane + i*32] * Wout[lane + i*32];
#pragma unroll
    for (int o = 16; o; o >>= 1) acc += __shfl_xor_sync(0xffffffffu, acc, o);
    if (lane == 0) {
        float z = acc + bout[0];
        g_density[w] = 1.f / (1.f + __expf(-z));
    }
}

// ---------------- encoder ctx + ctx @ Wc ----------------
__global__ void k_ctxw(const float* __restrict__ enc,
                       const float* __restrict__ mask,
                       const float* __restrict__ Ws,
                       const float* __restrict__ bs,
                       const float* __restrict__ Wc) {
    int b = blockIdx.x;
    int j = threadIdx.x;
    __shared__ float se[2*SS];
    __shared__ float sm[SS];
    __shared__ float sctx[HIDN];
    for (int i = j; i < 2*SS; i += 256) se[i] = enc[b*2*SS + i];
    for (int i = j; i < SS;   i += 256) sm[i] = mask[b*SS + i];
    __syncthreads();
    float w0 = Ws[j], w1 = Ws[HIDN + j], bj = bs[j];
    float acc = 0.f, msum = 0.f;
    for (int s = 0; s < SS; s++) {
        float mk = sm[s];
        msum += mk;
        float v = fmaxf(se[2*s]*w0 + se[2*s+1]*w1 + bj, 0.f);
        acc += mk * v;
    }
    sctx[j] = acc / fmaxf(msum, 1.f);
    __syncthreads();
    float a2 = 0.f;
    for (int k = 0; k < HIDN; k++) a2 += sctx[k] * Wc[k*HIDN + j];
    g_cwc[b*HIDN + j] = a2;
}

// ------- initial states + density/mesh replication -------
__global__ void k_init(const float* __restrict__ mesh,
                       const float* __restrict__ Wm,
                       const float* __restrict__ bm,
                       const float* __restrict__ Wo,
                       const float* __restrict__ bo,
                       float* __restrict__ out) {
    int b = blockIdx.y;
    int j = threadIdx.x;
    __shared__ __align__(16) float sW0[HIDN], sW1[HIDN], sW2[HIDN], sWo[HIDN], sC[HIDN];
    sW0[j] = Wm[j];
    sW1[j] = Wm[HIDN + j];
    sW2[j] = Wm[2*HIDN + j];
    sWo[j] = Wo[j];
    sC[j]  = g_cwc[b*HIDN + j] + bm[j];
    __syncthreads();

    int m[4]; bool v[4];
    float be[4], al[4], d[4], acc[4];
#pragma unroll
    for (int q = 0; q < 4; q++) {
        m[q] = blockIdx.x*1024 + q*256 + j;
        v[q] = m[q] < M_PTS;
        int mm = v[q] ? m[q] : 0;
        be[q] = mesh[2*mm];
        al[q] = mesh[2*mm + 1];
        d[q]  = g_density[mm];
        acc[q] = 0.f;
    }

    const float4* w0 = (const float4*)sW0;
    const float4* w1 = (const float4*)sW1;
    const float4* w2 = (const float4*)sW2;
    const float4* wo = (const float4*)sWo;
    const float4* cc = (const float4*)sC;
#pragma unroll 2
    for (int qq = 0; qq < HIDN/4; qq++) {
        float4 a0 = w0[qq], a1 = w1[qq], a2 = w2[qq], ao = wo[qq], ac = cc[qq];
#pragma unroll
        for (int q = 0; q < 4; q++) {
            acc[q] += fmaxf(ac.x + be[q]*a0.x + al[q]*a1.x + d[q]*a2.x, 0.f) * ao.x;
            acc[q] += fmaxf(ac.y + be[q]*a0.y + al[q]*a1.y + d[q]*a2.y, 0.f) * ao.y;
            acc[q] += fmaxf(ac.z + be[q]*a0.z + al[q]*a1.z + d[q]*a2.z, 0.f) * ao.z;
            acc[q] += fmaxf(ac.w + be[q]*a0.w + al[q]*a1.w + d[q]*a2.w, 0.f) * ao.w;
        }
    }
    float bo0 = bo[0];
#pragma unroll
    for (int q = 0; q < 4; q++) {
        if (!v[q]) continue;
        float is = tanhf(acc[q] + bo0);
        g_init[b*M_PTS + m[q]] = is;
        out[OFF_IS + (size_t)b*M_PTS + m[q]] = is;
        out[OFF_D  + (size_t)b*M_PTS + m[q]] = d[q];
        ((float2*)out)[(OFF_MESH >> 1) + (size_t)b*M_PTS + m[q]] = make_float2(be[q], al[q]);
    }
}

// ------- relay scan: 2D triangle tiles, 256 thr, combined vote -------
__global__ void __launch_bounds__(256) k_scan(const float* __restrict__ dec,
                                              const float* __restrict__ mesh) {
    __shared__ __align__(16) float sh_h[TT];
    __shared__ __align__(16) float tile[256*TSTR];
    __shared__ float aux[8][TC];
    int b = blockIdx.y;
    int tid = threadIdx.x;

    int tile_id = blockIdx.x;
    int tb = 0, rem = tile_id;
    while (rem >= 7 - tb) { rem -= 7 - tb; tb++; }
    int ta = tb + rem;

    int ib = tb*TDIM + (tid >> 4);
    int ia = ta*TDIM + (tid & 15);
    bool valid = (ib < GRID_N) && (ia < GRID_N) && (ia >= ib);
    int idx = 0;
    if (valid) idx = ib*GRID_N - (ib*(ib-1))/2 + (ia - ib);

    for (int t = tid; t < TT; t += 256) sh_h[t] = dec[b*TT + t];

    float be = valid ? mesh[2*idx]     : -2.f;
    float al = valid ? mesh[2*idx + 1] :  2.f;
    float d  = valid ? g_density[idx]  :  0.f;
    float sg = valid ? d * g_init[b*M_PTS + idx] : 0.f;
    float nd = -d;
    __syncthreads();

    float* myrow = &tile[tid*TSTR];
    int rcol  = tid & (TC-1);
    int rbase = (tid >> 5) * 32;
    float* gout = &g_bpart[((size_t)b*NTILES + blockIdx.x)*TT];

    for (int c0 = 0; c0 < TT; c0 += TC) {
#pragma unroll 2
        for (int t4 = 0; t4 < TC; t4 += 4) {
            float4 h4 = *(const float4*)&sh_h[c0 + t4];
            float o[4];
            float hts[4] = {h4.x, h4.y, h4.z, h4.w};
#pragma unroll
            for (int u = 0; u < 4; u++) {
                float ht = hts[u];
                float xu = ht - al;
                float xd = be - ht;
                bool nearany = (fabsf(xu) < CUT) | (fabsf(xd) < CUT);
                if (__any_sync(0xffffffffu, nearany)) {
                    float wu = 0.5f*fast_tanh(500.f*xu) + 0.5f;
                    float wd = 0.5f*fast_tanh(500.f*xd) + 0.5f;
                    sg += wu * (d  - sg);
                    sg += wd * (nd - sg);
                } else {
                    if (xu > 0.f) sg = d;
                    if (xd > 0.f) sg = nd;
                }
                o[u] = sg;
            }
            *(float4*)&myrow[t4] = make_float4(o[0], o[1], o[2], o[3]);
        }
        __syncthreads();
        float a = 0.f;
#pragma unroll 8
        for (int i = 0; i < 32; i++)
            a += tile[(rbase + i)*TSTR + rcol];
        aux[tid >> 5][rcol] = a;
        __syncthreads();
        if (tid < TC) {
            float g = 0.f;
#pragma unroll
            for (int w = 0; w < 8; w++) g += aux[w][tid];
            gout[c0 + tid] = g;
        }
        __syncthreads();
    }
}

// ---------------- final ----------------
__global__ void k_final(const float* __restrict__ dec,
                        const float* __restrict__ hraw,
                        const float* __restrict__ mraw,
                        const float* __restrict__ oraw,
                        float* __restrict__ out) {
    __shared__ float sred[256];
    int tid = threadIdx.x;
    float a = 0.f;
    for (int i = tid; i < M_PTS; i += 256) a += g_density[i];
    sred[tid] = a;
    __syncthreads();
    for (int o = 128; o; o >>= 1) {
        if (tid < o) sred[tid] += sred[tid + o];
        __syncthreads();
    }
    float dsum = sred[0];

    int i = blockIdx.x*256 + tid;
    int b = i >> 10, t = i & 1023;
    float acc = 0.f;
#pragma unroll
    for (int k = 0; k < NTILES; k++)
        acc += g_bpart[((size_t)b*NTILES + k)*TT + t];
    float mv = acc / dsum;
    float h = dec[i];
    float hs  = 10.f / (1.f + __expf(-hraw[0]));
    float ms  = 10.f / (1.f + __expf(-mraw[0]));
    float off = -10.f + 20.f / (1.f + __expf(-oraw[0]));
    out[OFF_BOUT + i] = hs*h + ms*mv + off;
    out[OFF_M + i] = mv;
}

// ---------------- launch ----------------
extern "C" void kernel_launch(void* const* d_in, const int* in_sizes, int n_in,
                              void* d_out, int out_size) {
    (void)in_sizes; (void)n_in; (void)out_size;
    const float* enc   = (const float*)d_in[0];
    const float* dec   = (const float*)d_in[1];
    const float* msk   = (const float*)d_in[2];
    const float* mesh  = (const float*)d_in[3];
    const float* dWin  = (const float*)d_in[4];
    const float* dbin  = (const float*)d_in[5];
    const float* dWr   = (const float*)d_in[6];
    const float* dbr   = (const float*)d_in[7];
    const float* dWout = (const float*)d_in[8];
    const float* dbout = (const float*)d_in[9];
    const float* eWs   = (const float*)d_in[10];
    const float* ebs   = (const float*)d_in[11];
    const float* eWm   = (const float*)d_in[12];
    const float* eWc   = (const float*)d_in[13];
    const float* ebm   = (const float*)d_in[14];
    const float* eWo   = (const float*)d_in[15];
    const float* ebo   = (const float*)d_in[16];
    const float* hraw  = (const float*)d_in[17];
    const float* mraw  = (const float*)d_in[18];
    const float* oraw  = (const float*)d_in[19];
    float* out = (float*)d_out;

    // density MLP (tensor path)
    k_wsplit<<<768, 256>>>(dWr);
    k_dens_in<<<M_PTS, 256>>>(mesh, dWin, dbin);
    dim3 gres(41, 4);
    k_res_tc<<<gres, 256>>>(dbr + 0*HIDN, 0, 0, 0);  // xhi/xlo -> yhi/ylo
    k_res_tc<<<gres, 256>>>(dbr + 1*HIDN, 1, 1, 0);  // yhi/ylo -> xhi/xlo
    k_res_tc<<<gres, 256>>>(dbr + 2*HIDN, 0, 2, 1);  // -> yhi/ylo + g_y fp32
    k_dens_out<<<644, 256>>>(dWout, dbout);

    // encoder + initial states
    k_ctxw<<<BB, 256>>>(enc, msk, eWs, ebs, eWc);
    dim3 ginit(6, BB);
    k_init<<<ginit, 256>>>(mesh, eWm, ebm, eWo, ebo, out);

    // relay scan + final
    dim3 gscan(NTILES, BB);
    k_scan<<<gscan, 256>>>(dec, mesh);
    k_final<<<64, 256>>>(dec, hraw, mraw, oraw, out);
}

// round 11
// speedup vs baseline: 1.0971x; 1.0971x over previous
#include <cuda_runtime.h>
#include <cstdint>

#define M_PTS 5151
#define HIDN  256
#define BB    16
#define SS    256
#define TT    1024
#define GRID_N 101
#define TDIM   16
#define NTILES 28
#define TC     32
#define TSTR   36
#define CUT 0.018f

#define XSTR 260          // X smem row stride (conflict-free A-frag)
#define BSTR 264          // W smem row stride (conflict-free B-frag)
#define MLP_SMEM_FLOATS (2*32*XSTR + 2*16*BSTR)   // 16640 + 8448 = 25088
#define MLP_SMEM_BYTES  (MLP_SMEM_FLOATS*4)       // 100352

#define OFF_BOUT 0
#define OFF_D    16384
#define OFF_M    (OFF_D + BB*M_PTS)
#define OFF_IS   (OFF_M + BB*TT)
#define OFF_MESH (OFF_IS + BB*M_PTS)

// ---------------- scratch ----------------
__device__ float g_density[M_PTS];
__device__ float g_cwc[BB*HIDN];
__device__ float g_init[BB*M_PTS];
__device__ float g_bpart[BB*NTILES*TT];

__device__ __forceinline__ float fast_tanh(float x) {
    float r;
    asm("tanh.approx.f32 %0, %1;" : "=f"(r) : "f"(x));
    return r;
}

__device__ __forceinline__ float to_tf32(float x) {
    uint32_t r;
    asm("cvt.rna.tf32.f32 %0, %1;" : "=r"(r) : "f"(x));
    return __uint_as_float(r);
}

__device__ __forceinline__ void mma_tf32(float* c, const float* a, const float* b) {
    asm volatile(
        "mma.sync.aligned.m16n8k8.row.col.f32.tf32.tf32.f32 "
        "{%0,%1,%2,%3}, {%4,%5,%6,%7}, {%8,%9}, {%0,%1,%2,%3};"
        : "+f"(c[0]), "+f"(c[1]), "+f"(c[2]), "+f"(c[3])
        : "r"(__float_as_uint(a[0])), "r"(__float_as_uint(a[1])),
          "r"(__float_as_uint(a[2])), "r"(__float_as_uint(a[3])),
          "r"(__float_as_uint(b[0])), "r"(__float_as_uint(b[1])));
}

// ============ fused density MLP: dens_in + 3 res layers + dens_out =======
// Block = 32 mesh rows. X (hi/lo tf32) lives in smem, updated in place.
__global__ void __launch_bounds__(256, 2) k_mlp(
    const float* __restrict__ mesh,
    const float* __restrict__ Win, const float* __restrict__ bin,
    const float* __restrict__ Wr,  const float* __restrict__ br,
    const float* __restrict__ Wout, const float* __restrict__ bout)
{
    extern __shared__ __align__(16) float smf[];
    float* Xh = smf;                   // 32 x XSTR
    float* Xl = smf + 32*XSTR;
    float* Bh = smf + 2*32*XSTR;       // 16 x BSTR
    float* Bl = smf + 2*32*XSTR + 16*BSTR;

    int tid = threadIdx.x;
    int bm = blockIdx.x * 32;

    // ---- dens_in: x = relu(mesh @ Win + bin), tf32-split into smem ----
    {
        int r  = tid >> 3;
        int c0 = (tid & 7) * 32;
        int gr = bm + r;
        bool ok = gr < M_PTS;
        float be = ok ? mesh[2*gr]   : 0.f;
        float al = ok ? mesh[2*gr+1] : 0.f;
#pragma unroll 8
        for (int c = c0; c < c0 + 32; c++) {
            float v = ok ? fmaxf(be*Win[c] + al*Win[HIDN + c] + bin[c], 0.f) : 0.f;
            float hi = to_tf32(v);
            Xh[r*XSTR + c] = hi;
            Xl[r*XSTR + c] = to_tf32(v - hi);
        }
    }
    __syncthreads();

    int warp = tid >> 5, lane = tid & 31;
    int lr = lane >> 2, lc = lane & 3;
    int n_base = warp * 32;            // warp covers cols [32w, 32w+32)

    // W staging mapping: 16x256 fp32 = 1024 float4; 4 per thread
    int wp[4], wrow[4], wcol[4];
#pragma unroll
    for (int u = 0; u < 4; u++) {
        wp[u] = tid + u*256;
        wrow[u] = wp[u] >> 6;
        wcol[u] = (wp[u] & 63) * 4;
    }

    for (int layer = 0; layer < 3; layer++) {
        const float* W = Wr + layer*HIDN*HIDN;
        const float* bias = br + layer*HIDN;

        float acc[2][4][4];
#pragma unroll
        for (int t = 0; t < 2; t++)
#pragma unroll
            for (int j = 0; j < 4; j++)
#pragma unroll
                for (int q = 0; q < 4; q++) acc[t][j][q] = 0.f;

        float4 pw[4];
#pragma unroll
        for (int u = 0; u < 4; u++)
            pw[u] = *(const float4*)&W[wrow[u]*HIDN + wcol[u]];

        for (int ch = 0; ch < 16; ch++) {
            // convert + store current W chunk
#pragma unroll
            for (int u = 0; u < 4; u++) {
                float4 v = pw[u];
                float4 h4, l4;
                h4.x = to_tf32(v.x); l4.x = to_tf32(v.x - h4.x);
                h4.y = to_tf32(v.y); l4.y = to_tf32(v.y - h4.y);
                h4.z = to_tf32(v.z); l4.z = to_tf32(v.z - h4.z);
                h4.w = to_tf32(v.w); l4.w = to_tf32(v.w - h4.w);
                *(float4*)&Bh[wrow[u]*BSTR + wcol[u]] = h4;
                *(float4*)&Bl[wrow[u]*BSTR + wcol[u]] = l4;
            }
            __syncthreads();

            if (ch < 15) {
                int k0n = (ch + 1) * 16;
#pragma unroll
                for (int u = 0; u < 4; u++)
                    pw[u] = *(const float4*)&W[(k0n + wrow[u])*HIDN + wcol[u]];
            }

            int Kc = ch * 16;
#pragma unroll
            for (int kk = 0; kk < 16; kk += 8) {
                int K = Kc + kk;
                float ah[2][4], al2[2][4];
#pragma unroll
                for (int t = 0; t < 2; t++) {
                    int r = t*16 + lr;
                    ah[t][0]  = Xh[ r     *XSTR + K + lc];
                    ah[t][1]  = Xh[(r + 8)*XSTR + K + lc];
                    ah[t][2]  = Xh[ r     *XSTR + K + lc + 4];
                    ah[t][3]  = Xh[(r + 8)*XSTR + K + lc + 4];
                    al2[t][0] = Xl[ r     *XSTR + K + lc];
                    al2[t][1] = Xl[(r + 8)*XSTR + K + lc];
                    al2[t][2] = Xl[ r     *XSTR + K + lc + 4];
                    al2[t][3] = Xl[(r + 8)*XSTR + K + lc + 4];
                }
                float bh[4][2], bl[4][2];
#pragma unroll
                for (int j = 0; j < 4; j++) {
                    int n = n_base + j*8 + lr;
                    bh[j][0] = Bh[(kk + lc    )*BSTR + n];
                    bh[j][1] = Bh[(kk + lc + 4)*BSTR + n];
                    bl[j][0] = Bl[(kk + lc    )*BSTR + n];
                    bl[j][1] = Bl[(kk + lc + 4)*BSTR + n];
                }
#pragma unroll
                for (int t = 0; t < 2; t++)
#pragma unroll
                    for (int j = 0; j < 4; j++) {
                        mma_tf32(acc[t][j], ah[t],  bh[j]);
                        mma_tf32(acc[t][j], ah[t],  bl[j]);
                        mma_tf32(acc[t][j], al2[t], bh[j]);
                    }
            }
            __syncthreads();
        }

        // ---- epilogue: x = x + relu(acc + bias), in place ----
#pragma unroll
        for (int t = 0; t < 2; t++)
#pragma unroll
            for (int j = 0; j < 4; j++) {
                int c = n_base + j*8 + 2*lc;
                float2 bz = *(const float2*)&bias[c];
#pragma unroll
                for (int h = 0; h < 2; h++) {
                    int r = t*16 + lr + 8*h;
                    int g = r*XSTR + c;
                    float y0 = (Xh[g]   + Xl[g])   + fmaxf(acc[t][j][2*h]   + bz.x, 0.f);
                    float y1 = (Xh[g+1] + Xl[g+1]) + fmaxf(acc[t][j][2*h+1] + bz.y, 0.f);
                    float h0 = to_tf32(y0), h1 = to_tf32(y1);
                    Xh[g]   = h0; Xl[g]   = to_tf32(y0 - h0);
                    Xh[g+1] = h1; Xl[g+1] = to_tf32(y1 - h1);
                }
            }
        __syncthreads();
    }

    // ---- dens_out: density = sigmoid(y . Wout + bout) ----
    {
        float b0 = bout[0];
#pragma unroll
        for (int rr = 0; rr < 4; rr++) {
            int r = warp*4 + rr;
            int gr = bm + r;
            float a = 0.f;
#pragma unroll
            for (int i = 0; i < 8; i++) {
                int c = lane + i*32;
                a += (Xh[r*XSTR + c] + Xl[r*XSTR + c]) * Wout[c];
            }
#pragma unroll
            for (int o = 16; o; o >>= 1) a += __shfl_xor_sync(0xffffffffu, a, o);
            if (lane == 0 && gr < M_PTS)
                g_density[gr] = 1.f / (1.f + __expf(-(a + b0)));
        }
    }
}

// ---------------- encoder ctx + ctx @ Wc ----------------
__global__ void k_ctxw(const float* __restrict__ enc,
                       const float* __restrict__ mask,
                       const float* __restrict__ Ws,
                       const float* __restrict__ bs,
                       const float* __restrict__ Wc) {
    int b = blockIdx.x;
    int j = threadIdx.x;
    __shared__ float se[2*SS];
    __shared__ float sm[SS];
    __shared__ float sctx[HIDN];
    for (int i = j; i < 2*SS; i += 256) se[i] = enc[b*2*SS + i];
    for (int i = j; i < SS;   i += 256) sm[i] = mask[b*SS + i];
    __syncthreads();
    float w0 = Ws[j], w1 = Ws[HIDN + j], bj = bs[j];
    float acc = 0.f, msum = 0.f;
    for (int s = 0; s < SS; s++) {
        float mk = sm[s];
        msum += mk;
        float v = fmaxf(se[2*s]*w0 + se[2*s+1]*w1 + bj, 0.f);
        acc += mk * v;
    }
    sctx[j] = acc / fmaxf(msum, 1.f);
    __syncthreads();
    float a2 = 0.f;
    for (int k = 0; k < HIDN; k++) a2 += sctx[k] * Wc[k*HIDN + j];
    g_cwc[b*HIDN + j] = a2;
}

// ------- initial states + density/mesh replication -------
__global__ void k_init(const float* __restrict__ mesh,
                       const float* __restrict__ Wm,
                       const float* __restrict__ bm,
                       const float* __restrict__ Wo,
                       const float* __restrict__ bo,
                       float* __restrict__ out) {
    int b = blockIdx.y;
    int j = threadIdx.x;
    __shared__ __align__(16) float sW0[HIDN], sW1[HIDN], sW2[HIDN], sWo[HIDN], sC[HIDN];
    sW0[j] = Wm[j];
    sW1[j] = Wm[HIDN + j];
    sW2[j] = Wm[2*HIDN + j];
    sWo[j] = Wo[j];
    sC[j]  = g_cwc[b*HIDN + j] + bm[j];
    __syncthreads();

    int m[4]; bool v[4];
    float be[4], al[4], d[4], acc[4];
#pragma unroll
    for (int q = 0; q < 4; q++) {
        m[q] = blockIdx.x*1024 + q*256 + j;
        v[q] = m[q] < M_PTS;
        int mm = v[q] ? m[q] : 0;
        be[q] = mesh[2*mm];
        al[q] = mesh[2*mm + 1];
        d[q]  = g_density[mm];
        acc[q] = 0.f;
    }

    const float4* w0 = (const float4*)sW0;
    const float4* w1 = (const float4*)sW1;
    const float4* w2 = (const float4*)sW2;
    const float4* wo = (const float4*)sWo;
    const float4* cc = (const float4*)sC;
#pragma unroll 2
    for (int qq = 0; qq < HIDN/4; qq++) {
        float4 a0 = w0[qq], a1 = w1[qq], a2 = w2[qq], ao = wo[qq], ac = cc[qq];
#pragma unroll
        for (int q = 0; q < 4; q++) {
            acc[q] += fmaxf(ac.x + be[q]*a0.x + al[q]*a1.x + d[q]*a2.x, 0.f) * ao.x;
            acc[q] += fmaxf(ac.y + be[q]*a0.y + al[q]*a1.y + d[q]*a2.y, 0.f) * ao.y;
            acc[q] += fmaxf(ac.z + be[q]*a0.z + al[q]*a1.z + d[q]*a2.z, 0.f) * ao.z;
            acc[q] += fmaxf(ac.w + be[q]*a0.w + al[q]*a1.w + d[q]*a2.w, 0.f) * ao.w;
        }
    }
    float bo0 = bo[0];
#pragma unroll
    for (int q = 0; q < 4; q++) {
        if (!v[q]) continue;
        float is = tanhf(acc[q] + bo0);
        g_init[b*M_PTS + m[q]] = is;
        out[OFF_IS + (size_t)b*M_PTS + m[q]] = is;
        out[OFF_D  + (size_t)b*M_PTS + m[q]] = d[q];
        ((float2*)out)[(OFF_MESH >> 1) + (size_t)b*M_PTS + m[q]] = make_float2(be[q], al[q]);
    }
}

// ------- relay scan: 2D triangle tiles, 256 thr, combined vote -------
__global__ void __launch_bounds__(256) k_scan(const float* __restrict__ dec,
                                              const float* __restrict__ mesh) {
    __shared__ __align__(16) float sh_h[TT];
    __shared__ __align__(16) float tile[256*TSTR];
    __shared__ float aux[8][TC];
    int b = blockIdx.y;
    int tid = threadIdx.x;

    int tile_id = blockIdx.x;
    int tb = 0, rem = tile_id;
    while (rem >= 7 - tb) { rem -= 7 - tb; tb++; }
    int ta = tb + rem;

    int ib = tb*TDIM + (tid >> 4);
    int ia = ta*TDIM + (tid & 15);
    bool valid = (ib < GRID_N) && (ia < GRID_N) && (ia >= ib);
    int idx = 0;
    if (valid) idx = ib*GRID_N - (ib*(ib-1))/2 + (ia - ib);

    for (int t = tid; t < TT; t += 256) sh_h[t] = dec[b*TT + t];

    float be = valid ? mesh[2*idx]     : -2.f;
    float al = valid ? mesh[2*idx + 1] :  2.f;
    float d  = valid ? g_density[idx]  :  0.f;
    float sg = valid ? d * g_init[b*M_PTS + idx] : 0.f;
    float nd = -d;
    __syncthreads();

    float* myrow = &tile[tid*TSTR];
    int rcol  = tid & (TC-1);
    int rbase = (tid >> 5) * 32;
    float* gout = &g_bpart[((size_t)b*NTILES + blockIdx.x)*TT];

    for (int c0 = 0; c0 < TT; c0 += TC) {
#pragma unroll 2
        for (int t4 = 0; t4 < TC; t4 += 4) {
            float4 h4 = *(const float4*)&sh_h[c0 + t4];
            float o[4];
            float hts[4] = {h4.x, h4.y, h4.z, h4.w};
#pragma unroll
            for (int u = 0; u < 4; u++) {
                float ht = hts[u];
                float xu = ht - al;
                float xd = be - ht;
                bool nearany = (fabsf(xu) < CUT) | (fabsf(xd) < CUT);
                if (__any_sync(0xffffffffu, nearany)) {
                    float wu = 0.5f*fast_tanh(500.f*xu) + 0.5f;
                    float wd = 0.5f*fast_tanh(500.f*xd) + 0.5f;
                    sg += wu * (d  - sg);
                    sg += wd * (nd - sg);
                } else {
                    if (xu > 0.f) sg = d;
                    if (xd > 0.f) sg = nd;
                }
                o[u] = sg;
            }
            *(float4*)&myrow[t4] = make_float4(o[0], o[1], o[2], o[3]);
        }
        __syncthreads();
        float a = 0.f;
#pragma unroll 8
        for (int i = 0; i < 32; i++)
            a += tile[(rbase + i)*TSTR + rcol];
        aux[tid >> 5][rcol] = a;
        __syncthreads();
        if (tid < TC) {
            float g = 0.f;
#pragma unroll
            for (int w = 0; w < 8; w++) g += aux[w][tid];
            gout[c0 + tid] = g;
        }
        __syncthreads();
    }
}

// ---------------- final ----------------
__global__ void k_final(const float* __restrict__ dec,
                        const float* __restrict__ hraw,
                        const float* __restrict__ mraw,
                        const float* __restrict__ oraw,
                        float* __restrict__ out) {
    __shared__ float sred[256];
    int tid = threadIdx.x;
    float a = 0.f;
    for (int i = tid; i < M_PTS; i += 256) a += g_density[i];
    sred[tid] = a;
    __syncthreads();
    for (int o = 128; o; o >>= 1) {
        if (tid < o) sred[tid] += sred[tid + o];
        __syncthreads();
    }
    float dsum = sred[0];

    int i = blockIdx.x*256 + tid;
    int b = i >> 10, t = i & 1023;
    float acc = 0.f;
#pragma unroll
    for (int k = 0; k < NTILES; k++)
        acc += g_bpart[((size_t)b*NTILES + k)*TT + t];
    float mv = acc / dsum;
    float h = dec[i];
    float hs  = 10.f / (1.f + __expf(-hraw[0]));
    float ms  = 10.f / (1.f + __expf(-mraw[0]));
    float off = -10.f + 20.f / (1.f + __expf(-oraw[0]));
    out[OFF_BOUT + i] = hs*h + ms*mv + off;
    out[OFF_M + i] = mv;
}

// ---------------- launch ----------------
extern "C" void kernel_launch(void* const* d_in, const int* in_sizes, int n_in,
                              void* d_out, int out_size) {
    (void)in_sizes; (void)n_in; (void)out_size;
    const float* enc   = (const float*)d_in[0];
    const float* dec   = (const float*)d_in[1];
    const float* msk   = (const float*)d_in[2];
    const float* mesh  = (const float*)d_in[3];
    const float* dWin  = (const float*)d_in[4];
    const float* dbin  = (const float*)d_in[5];
    const float* dWr   = (const float*)d_in[6];
    const float* dbr   = (const float*)d_in[7];
    const float* dWout = (const float*)d_in[8];
    const float* dbout = (const float*)d_in[9];
    const float* eWs   = (const float*)d_in[10];
    const float* ebs   = (const float*)d_in[11];
    const float* eWm   = (const float*)d_in[12];
    const float* eWc   = (const float*)d_in[13];
    const float* ebm   = (const float*)d_in[14];
    const float* eWo   = (const float*)d_in[15];
    const float* ebo   = (const float*)d_in[16];
    const float* hraw  = (const float*)d_in[17];
    const float* mraw  = (const float*)d_in[18];
    const float* oraw  = (const float*)d_in[19];
    float* out = (float*)d_out;

    static int smem_set = 0;
    if (!smem_set) {
        cudaFuncSetAttribute(k_mlp, cudaFuncAttributeMaxDynamicSharedMemorySize,
                             MLP_SMEM_BYTES);
        smem_set = 1;
    }

    // fused density MLP (dens_in + 3 residual layers + dens_out)
    k_mlp<<<161, 256, MLP_SMEM_BYTES>>>(mesh, dWin, dbin, dWr, dbr, dWout, dbout);

    // encoder + initial states (+ density/mesh output replication)
    k_ctxw<<<BB, 256>>>(enc, msk, eWs, ebs, eWc);
    dim3 ginit(6, BB);
    k_init<<<ginit, 256>>>(mesh, eWm, ebm, eWo, ebo, out);

    // relay scan + final
    dim3 gscan(NTILES, BB);
    k_scan<<<gscan, 256>>>(dec, mesh);
    k_final<<<64, 256>>>(dec, hraw, mraw, oraw, out);
}

// round 12
// speedup vs baseline: 1.2774x; 1.1644x over previous
#include <cuda_runtime.h>
#include <cstdint>

#define M_PTS 5151
#define HIDN  256
#define BB    16
#define SS    256
#define TT    1024
#define GRID_N 101
#define NTILES 16          // 32beta x 16alpha triangle tiles
#define TC     32
#define TSTR   36
#define CUT 0.018f

// k_mlp smem (floats): Xh_p/Xl_p 32x132 uint32 each; Bh_p/Bl_p 8x264 each
#define XP_STR 132
#define BP_STR 264
#define SM_XH 0
#define SM_XL (32*XP_STR)
#define SM_BH (2*32*XP_STR)
#define SM_BL (2*32*XP_STR + 8*BP_STR)
#define MLP_SMEM_WORDS (2*32*XP_STR + 2*8*BP_STR)   // 8448+4224 = 12672
#define MLP_SMEM_BYTES (MLP_SMEM_WORDS*4)           // 50688

#define OFF_BOUT 0
#define OFF_D    16384
#define OFF_M    (OFF_D + BB*M_PTS)
#define OFF_IS   (OFF_M + BB*TT)
#define OFF_MESH (OFF_IS + BB*M_PTS)

// ---------------- scratch ----------------
__device__ uint32_t g_wph[3*128*HIDN];   // W bf16-hi, k-pairs packed
__device__ uint32_t g_wpl[3*128*HIDN];   // W bf16-lo
__device__ float g_density[M_PTS];
__device__ float g_cwc[BB*HIDN];
__device__ float g_init[BB*M_PTS];
__device__ float g_bpart[BB*NTILES*TT];

__device__ __forceinline__ float fast_tanh(float x) {
    float r;
    asm("tanh.approx.f32 %0, %1;" : "=f"(r) : "f"(x));
    return r;
}

__device__ __forceinline__ float bf16lo_f(uint32_t p) {   // low bf16 -> f32
    return __uint_as_float(p << 16);
}
__device__ __forceinline__ float bf16hi_f(uint32_t p) {   // high bf16 -> f32
    return __uint_as_float(p & 0xffff0000u);
}
// pack (x0,x1) into bf16x2 hi-part, produce lo-part residual pack
__device__ __forceinline__ uint32_t pack_split(float x0, float x1, uint32_t* lo) {
    uint32_t hp;
    asm("cvt.rn.bf16x2.f32 %0, %1, %2;" : "=r"(hp) : "f"(x1), "f"(x0));
    float h0 = bf16lo_f(hp), h1 = bf16hi_f(hp);
    uint32_t lp;
    asm("cvt.rn.bf16x2.f32 %0, %1, %2;" : "=r"(lp) : "f"(x1 - h1), "f"(x0 - h0));
    *lo = lp;
    return hp;
}

__device__ __forceinline__ void mma_bf16(float* c, const uint32_t* a, const uint32_t* b) {
    asm volatile(
        "mma.sync.aligned.m16n8k16.row.col.f32.bf16.bf16.f32 "
        "{%0,%1,%2,%3}, {%4,%5,%6,%7}, {%8,%9}, {%0,%1,%2,%3};"
        : "+f"(c[0]), "+f"(c[1]), "+f"(c[2]), "+f"(c[3])
        : "r"(a[0]), "r"(a[1]), "r"(a[2]), "r"(a[3]),
          "r"(b[0]), "r"(b[1]));
}

// ---------------- W split+pack (once): Wr[3][256][256] -> packed k-pairs ----
__global__ void k_wsplitp(const float* __restrict__ Wr) {
    int i = blockIdx.x*256 + threadIdx.x;       // 0..98303
    if (i >= 3*128*HIDN) return;
    int l  = i >> 15;            // /32768
    int r2 = (i >> 8) & 127;     // k-pair
    int n  = i & 255;
    const float* base = Wr + l*HIDN*HIDN;
    float w0 = base[(2*r2  )*HIDN + n];
    float w1 = base[(2*r2+1)*HIDN + n];
    uint32_t lo;
    uint32_t hi = pack_split(w0, w1, &lo);
    g_wph[i] = hi;
    g_wpl[i] = lo;
}

// ===== fused density MLP: dens_in + 3 res layers (bf16 3-term) + dens_out ==
__global__ void __launch_bounds__(256) k_mlp(
    const float* __restrict__ mesh,
    const float* __restrict__ Win, const float* __restrict__ bin,
    const float* __restrict__ br,
    const float* __restrict__ Wout, const float* __restrict__ bout)
{
    extern __shared__ __align__(16) uint32_t smw[];
    uint32_t* Xh = smw + SM_XH;
    uint32_t* Xl = smw + SM_XL;
    uint32_t* Bh = smw + SM_BH;
    uint32_t* Bl = smw + SM_BL;

    int tid = threadIdx.x;
    int bm = blockIdx.x * 32;

    // ---- dens_in: x = relu(mesh @ Win + bin), bf16-split packed into smem --
    {
        int r  = tid >> 3;
        int c0 = (tid & 7) * 32;
        int gr = bm + r;
        bool ok = gr < M_PTS;
        float be = ok ? mesh[2*gr]   : 0.f;
        float al = ok ? mesh[2*gr+1] : 0.f;
#pragma unroll 4
        for (int p = 0; p < 16; p++) {
            int c = c0 + 2*p;
            float x0 = ok ? fmaxf(be*Win[c]   + al*Win[HIDN+c]   + bin[c],   0.f) : 0.f;
            float x1 = ok ? fmaxf(be*Win[c+1] + al*Win[HIDN+c+1] + bin[c+1], 0.f) : 0.f;
            uint32_t lo;
            uint32_t hi = pack_split(x0, x1, &lo);
            Xh[r*XP_STR + (c>>1)] = hi;
            Xl[r*XP_STR + (c>>1)] = lo;
        }
    }
    __syncthreads();

    int warp = tid >> 5, lane = tid & 31;
    int lr = lane >> 2, lc = lane & 3;
    int n_base = warp * 32;

    // W staging: 2048 uint32 per array per chunk; thread owns 8 consecutive
    int woff = tid * 8;
    int wr2  = woff >> 8;        // smem row 0..7
    int wcc  = woff & 255;

    for (int layer = 0; layer < 3; layer++) {
        const uint32_t* WPH = g_wph + layer*128*HIDN;
        const uint32_t* WPL = g_wpl + layer*128*HIDN;
        const float* bias = br + layer*HIDN;

        float acc[2][4][4];
#pragma unroll
        for (int t = 0; t < 2; t++)
#pragma unroll
            for (int j = 0; j < 4; j++)
#pragma unroll
                for (int q = 0; q < 4; q++) acc[t][j][q] = 0.f;

        uint4 ph0 = *(const uint4*)&WPH[woff];
        uint4 ph1 = *(const uint4*)&WPH[woff + 4];
        uint4 pl0 = *(const uint4*)&WPL[woff];
        uint4 pl1 = *(const uint4*)&WPL[woff + 4];

        for (int ch = 0; ch < 16; ch++) {
            *(uint4*)&Bh[wr2*BP_STR + wcc]     = ph0;
            *(uint4*)&Bh[wr2*BP_STR + wcc + 4] = ph1;
            *(uint4*)&Bl[wr2*BP_STR + wcc]     = pl0;
            *(uint4*)&Bl[wr2*BP_STR + wcc + 4] = pl1;
            __syncthreads();

            if (ch < 15) {
                int g = (ch + 1)*2048 + woff;
                ph0 = *(const uint4*)&WPH[g];
                ph1 = *(const uint4*)&WPH[g + 4];
                pl0 = *(const uint4*)&WPL[g];
                pl1 = *(const uint4*)&WPL[g + 4];
            }

            int k2b = ch * 8;
            uint32_t a_h[2][4], a_l[2][4];
#pragma unroll
            for (int t = 0; t < 2; t++) {
                int r = t*16 + lr;
                a_h[t][0] = Xh[ r     *XP_STR + k2b + lc];
                a_h[t][1] = Xh[(r + 8)*XP_STR + k2b + lc];
                a_h[t][2] = Xh[ r     *XP_STR + k2b + lc + 4];
                a_h[t][3] = Xh[(r + 8)*XP_STR + k2b + lc + 4];
                a_l[t][0] = Xl[ r     *XP_STR + k2b + lc];
                a_l[t][1] = Xl[(r + 8)*XP_STR + k2b + lc];
                a_l[t][2] = Xl[ r     *XP_STR + k2b + lc + 4];
                a_l[t][3] = Xl[(r + 8)*XP_STR + k2b + lc + 4];
            }
            uint32_t b_h[4][2], b_l[4][2];
#pragma unroll
            for (int j = 0; j < 4; j++) {
                int n = n_base + j*8 + lr;
                b_h[j][0] = Bh[ lc     *BP_STR + n];
                b_h[j][1] = Bh[(lc + 4)*BP_STR + n];
                b_l[j][0] = Bl[ lc     *BP_STR + n];
                b_l[j][1] = Bl[(lc + 4)*BP_STR + n];
            }
#pragma unroll
            for (int t = 0; t < 2; t++)
#pragma unroll
                for (int j = 0; j < 4; j++) {
                    mma_bf16(acc[t][j], a_h[t], b_h[j]);
                    mma_bf16(acc[t][j], a_h[t], b_l[j]);
                    mma_bf16(acc[t][j], a_l[t], b_h[j]);
                }
            __syncthreads();
        }

        // ---- epilogue: x = x + relu(acc + bias), in place (packed) ----
#pragma unroll
        for (int t = 0; t < 2; t++)
#pragma unroll
            for (int j = 0; j < 4; j++) {
                int c = n_base + j*8 + 2*lc;       // even
                int c2 = c >> 1;
                float2 bz = *(const float2*)&bias[c];
#pragma unroll
                for (int h = 0; h < 2; h++) {
                    int r = t*16 + lr + 8*h;
                    int g = r*XP_STR + c2;
                    uint32_t hp = Xh[g], lp = Xl[g];
                    float x0 = bf16lo_f(hp) + bf16lo_f(lp);
                    float x1 = bf16hi_f(hp) + bf16hi_f(lp);
                    float y0 = x0 + fmaxf(acc[t][j][2*h]   + bz.x, 0.f);
                    float y1 = x1 + fmaxf(acc[t][j][2*h+1] + bz.y, 0.f);
                    uint32_t lo;
                    Xh[g] = pack_split(y0, y1, &lo);
                    Xl[g] = lo;
                }
            }
        __syncthreads();
    }

    // ---- dens_out: density = sigmoid(y . Wout + bout) ----
    {
        float b0 = bout[0];
#pragma unroll
        for (int rr = 0; rr < 4; rr++) {
            int r = warp*4 + rr;
            int gr = bm + r;
            float a = 0.f;
#pragma unroll
            for (int i = 0; i < 4; i++) {
                int c2 = lane + i*32;
                uint32_t hp = Xh[r*XP_STR + c2], lp = Xl[r*XP_STR + c2];
                a += (bf16lo_f(hp) + bf16lo_f(lp)) * Wout[2*c2];
                a += (bf16hi_f(hp) + bf16hi_f(lp)) * Wout[2*c2+1];
            }
#pragma unroll
            for (int o = 16; o; o >>= 1) a += __shfl_xor_sync(0xffffffffu, a, o);
            if (lane == 0 && gr < M_PTS)
                g_density[gr] = 1.f / (1.f + __expf(-(a + b0)));
        }
    }
}

// ---------------- encoder ctx + ctx @ Wc ----------------
__global__ void k_ctxw(const float* __restrict__ enc,
                       const float* __restrict__ mask,
                       const float* __restrict__ Ws,
                       const float* __restrict__ bs,
                       const float* __restrict__ Wc) {
    int b = blockIdx.x;
    int j = threadIdx.x;
    __shared__ float se[2*SS];
    __shared__ float sm[SS];
    __shared__ float sctx[HIDN];
    for (int i = j; i < 2*SS; i += 256) se[i] = enc[b*2*SS + i];
    for (int i = j; i < SS;   i += 256) sm[i] = mask[b*SS + i];
    __syncthreads();
    float w0 = Ws[j], w1 = Ws[HIDN + j], bj = bs[j];
    float acc = 0.f, msum = 0.f;
    for (int s = 0; s < SS; s++) {
        float mk = sm[s];
        msum += mk;
        float v = fmaxf(se[2*s]*w0 + se[2*s+1]*w1 + bj, 0.f);
        acc += mk * v;
    }
    sctx[j] = acc / fmaxf(msum, 1.f);
    __syncthreads();
    float a2 = 0.f;
    for (int k = 0; k < HIDN; k++) a2 += sctx[k] * Wc[k*HIDN + j];
    g_cwc[b*HIDN + j] = a2;
}

// ------- initial states + density/mesh replication -------
__global__ void k_init(const float* __restrict__ mesh,
                       const float* __restrict__ Wm,
                       const float* __restrict__ bm,
                       const float* __restrict__ Wo,
                       const float* __restrict__ bo,
                       float* __restrict__ out) {
    int b = blockIdx.y;
    int j = threadIdx.x;
    __shared__ __align__(16) float sW0[HIDN], sW1[HIDN], sW2[HIDN], sWo[HIDN], sC[HIDN];
    sW0[j] = Wm[j];
    sW1[j] = Wm[HIDN + j];
    sW2[j] = Wm[2*HIDN + j];
    sWo[j] = Wo[j];
    sC[j]  = g_cwc[b*HIDN + j] + bm[j];
    __syncthreads();

    int m[4]; bool v[4];
    float be[4], al[4], d[4], acc[4];
#pragma unroll
    for (int q = 0; q < 4; q++) {
        m[q] = blockIdx.x*1024 + q*256 + j;
        v[q] = m[q] < M_PTS;
        int mm = v[q] ? m[q] : 0;
        be[q] = mesh[2*mm];
        al[q] = mesh[2*mm + 1];
        d[q]  = g_density[mm];
        acc[q] = 0.f;
    }

    const float4* w0 = (const float4*)sW0;
    const float4* w1 = (const float4*)sW1;
    const float4* w2 = (const float4*)sW2;
    const float4* wo = (const float4*)sWo;
    const float4* cc = (const float4*)sC;
#pragma unroll 2
    for (int qq = 0; qq < HIDN/4; qq++) {
        float4 a0 = w0[qq], a1 = w1[qq], a2 = w2[qq], ao = wo[qq], ac = cc[qq];
#pragma unroll
        for (int q = 0; q < 4; q++) {
            acc[q] += fmaxf(ac.x + be[q]*a0.x + al[q]*a1.x + d[q]*a2.x, 0.f) * ao.x;
            acc[q] += fmaxf(ac.y + be[q]*a0.y + al[q]*a1.y + d[q]*a2.y, 0.f) * ao.y;
            acc[q] += fmaxf(ac.z + be[q]*a0.z + al[q]*a1.z + d[q]*a2.z, 0.f) * ao.z;
            acc[q] += fmaxf(ac.w + be[q]*a0.w + al[q]*a1.w + d[q]*a2.w, 0.f) * ao.w;
        }
    }
    float bo0 = bo[0];
#pragma unroll
    for (int q = 0; q < 4; q++) {
        if (!v[q]) continue;
        float is = tanhf(acc[q] + bo0);
        g_init[b*M_PTS + m[q]] = is;
        out[OFF_IS + (size_t)b*M_PTS + m[q]] = is;
        out[OFF_D  + (size_t)b*M_PTS + m[q]] = d[q];
        ((float2*)out)[(OFF_MESH >> 1) + (size_t)b*M_PTS + m[q]] = make_float2(be[q], al[q]);
    }
}

// ------- relay scan: 32beta x 16alpha tiles, 2 beta-adjacent pts/thread ----
__global__ void __launch_bounds__(256) k_scan(const float* __restrict__ dec,
                                              const float* __restrict__ mesh) {
    __shared__ __align__(16) float sh_h[TT];
    __shared__ __align__(16) float tile[256*TSTR];
    __shared__ float aux[8][TC];
    int b = blockIdx.y;
    int tid = threadIdx.x;

    // tile_id -> (tb, ta): per-tb counts 7-2tb (7,5,3,1)
    int tb = 0, rem = blockIdx.x;
    while (rem >= 7 - 2*tb) { rem -= 7 - 2*tb; tb++; }
    int ta = 2*tb + rem;

    int ib0 = tb*32 + 2*(tid >> 4);
    int ib1 = ib0 + 1;
    int ia  = ta*16 + (tid & 15);
    bool v0 = (ib0 <= ia) && (ib0 < GRID_N) && (ia < GRID_N);
    bool v1 = (ib1 <= ia) && (ib1 < GRID_N) && (ia < GRID_N);
    int idx0 = v0 ? (ib0*GRID_N - (ib0*(ib0-1))/2 + ia - ib0) : 0;
    int idx1 = v1 ? (ib1*GRID_N - (ib1*(ib1-1))/2 + ia - ib1) : 0;

    for (int t = tid; t < TT; t += 256) sh_h[t] = dec[b*TT + t];

    float al  = v0 ? mesh[2*idx0 + 1] :  2.f;
    float be0 = v0 ? mesh[2*idx0]     : -2.f;
    float be1 = v1 ? mesh[2*idx1]     : -2.f;
    float d0  = v0 ? g_density[idx0]  :  0.f;
    float d1  = v1 ? g_density[idx1]  :  0.f;
    float sg0 = v0 ? d0 * g_init[b*M_PTS + idx0] : 0.f;
    float sg1 = v1 ? d1 * g_init[b*M_PTS + idx1] : 0.f;
    float nd0 = -d0, nd1 = -d1;
    __syncthreads();

    float* myrow = &tile[tid*TSTR];
    int rcol  = tid & (TC-1);
    int rbase = (tid >> 5) * 32;
    float* gout = &g_bpart[((size_t)b*NTILES + blockIdx.x)*TT];

    for (int c0 = 0; c0 < TT; c0 += TC) {
#pragma unroll 2
        for (int t4 = 0; t4 < TC; t4 += 4) {
            float4 h4 = *(const float4*)&sh_h[c0 + t4];
            float o[4];
            float hts[4] = {h4.x, h4.y, h4.z, h4.w};
#pragma unroll
            for (int u = 0; u < 4; u++) {
                float ht = hts[u];
                float xu  = ht - al;          // shared alpha
                float xd0 = be0 - ht;
                float xd1 = be1 - ht;
                bool nearany = (fabsf(xu) < CUT) | (fabsf(xd0) < CUT) | (fabsf(xd1) < CUT);
                if (__any_sync(0xffffffffu, nearany)) {
                    float wu  = 0.5f*fast_tanh(500.f*xu)  + 0.5f;
                    float wd0 = 0.5f*fast_tanh(500.f*xd0) + 0.5f;
                    float wd1 = 0.5f*fast_tanh(500.f*xd1) + 0.5f;
                    sg0 += wu  * (d0  - sg0);
                    sg1 += wu  * (d1  - sg1);
                    sg0 += wd0 * (nd0 - sg0);
                    sg1 += wd1 * (nd1 - sg1);
                } else {
                    if (xu  > 0.f) { sg0 = d0; sg1 = d1; }
                    if (xd0 > 0.f) sg0 = nd0;
                    if (xd1 > 0.f) sg1 = nd1;
                }
                o[u] = sg0 + sg1;
            }
            *(float4*)&myrow[t4] = make_float4(o[0], o[1], o[2], o[3]);
        }
        __syncthreads();
        float a = 0.f;
#pragma unroll 8
        for (int i = 0; i < 32; i++)
            a += tile[(rbase + i)*TSTR + rcol];
        aux[tid >> 5][rcol] = a;
        __syncthreads();
        if (tid < TC) {
            float g = 0.f;
#pragma unroll
            for (int w = 0; w < 8; w++) g += aux[w][tid];
            gout[c0 + tid] = g;
        }
        __syncthreads();
    }
}

// ---------------- final ----------------
__global__ void k_final(const float* __restrict__ dec,
                        const float* __restrict__ hraw,
                        const float* __restrict__ mraw,
                        const float* __restrict__ oraw,
                        float* __restrict__ out) {
    __shared__ float sred[256];
    int tid = threadIdx.x;
    float a = 0.f;
    for (int i = tid; i < M_PTS; i += 256) a += g_density[i];
    sred[tid] = a;
    __syncthreads();
    for (int o = 128; o; o >>= 1) {
        if (tid < o) sred[tid] += sred[tid + o];
        __syncthreads();
    }
    float dsum = sred[0];

    int i = blockIdx.x*256 + tid;
    int b = i >> 10, t = i & 1023;
    float acc = 0.f;
#pragma unroll
    for (int k = 0; k < NTILES; k++)
        acc += g_bpart[((size_t)b*NTILES + k)*TT + t];
    float mv = acc / dsum;
    float h = dec[i];
    float hs  = 10.f / (1.f + __expf(-hraw[0]));
    float ms  = 10.f / (1.f + __expf(-mraw[0]));
    float off = -10.f + 20.f / (1.f + __expf(-oraw[0]));
    out[OFF_BOUT + i] = hs*h + ms*mv + off;
    out[OFF_M + i] = mv;
}

// ---------------- launch ----------------
extern "C" void kernel_launch(void* const* d_in, const int* in_sizes, int n_in,
                              void* d_out, int out_size) {
    (void)in_sizes; (void)n_in; (void)out_size;
    const float* enc   = (const float*)d_in[0];
    const float* dec   = (const float*)d_in[1];
    const float* msk   = (const float*)d_in[2];
    const float* mesh  = (const float*)d_in[3];
    const float* dWin  = (const float*)d_in[4];
    const float* dbin  = (const float*)d_in[5];
    const float* dWr   = (const float*)d_in[6];
    const float* dbr   = (const float*)d_in[7];
    const float* dWout = (const float*)d_in[8];
    const float* dbout = (const float*)d_in[9];
    const float* eWs   = (const float*)d_in[10];
    const float* ebs   = (const float*)d_in[11];
    const float* eWm   = (const float*)d_in[12];
    const float* eWc   = (const float*)d_in[13];
    const float* ebm   = (const float*)d_in[14];
    const float* eWo   = (const float*)d_in[15];
    const float* ebo   = (const float*)d_in[16];
    const float* hraw  = (const float*)d_in[17];
    const float* mraw  = (const float*)d_in[18];
    const float* oraw  = (const float*)d_in[19];
    float* out = (float*)d_out;

    static int smem_set = 0;
    if (!smem_set) {
        cudaFuncSetAttribute(k_mlp, cudaFuncAttributeMaxDynamicSharedMemorySize,
                             MLP_SMEM_BYTES);
        smem_set = 1;
    }

    // W split/pack + fused density MLP
    k_wsplitp<<<384, 256>>>(dWr);
    k_mlp<<<161, 256, MLP_SMEM_BYTES>>>(mesh, dWin, dbin, dbr, dWout, dbout);

    // encoder + initial states (+ density/mesh output replication)
    k_ctxw<<<BB, 256>>>(enc, msk, eWs, ebs, eWc);
    dim3 ginit(6, BB);
    k_init<<<ginit, 256>>>(mesh, eWm, ebm, eWo, ebo, out);

    // relay scan + final
    dim3 gscan(NTILES, BB);
    k_scan<<<gscan, 256>>>(dec, mesh);
    k_final<<<64, 256>>>(dec, hraw, mraw, oraw, out);
}

// round 13
// speedup vs baseline: 1.3572x; 1.0624x over previous
#include <cuda_runtime.h>
#include <cstdint>

#define M_PTS 5151
#define HIDN  256
#define BB    16
#define SS    256
#define TT    1024
#define GRID_N 101
#define TDIM   16
#define NTILES 28          // 7x7 upper-triangular tiles of 16x16
#define TC     32
#define TSTR   36
#define CUT 0.018f

// k_mlp smem (words): Xh_p/Xl_p 32x132 uint32 each; Bh_p/Bl_p 8x264 each
#define XP_STR 132
#define BP_STR 264
#define SM_XH 0
#define SM_XL (32*XP_STR)
#define SM_BH (2*32*XP_STR)
#define SM_BL (2*32*XP_STR + 8*BP_STR)
#define MLP_SMEM_WORDS (2*32*XP_STR + 2*8*BP_STR)
#define MLP_SMEM_BYTES (MLP_SMEM_WORDS*4)           // 50688

#define OFF_BOUT 0
#define OFF_D    16384
#define OFF_M    (OFF_D + BB*M_PTS)
#define OFF_IS   (OFF_M + BB*TT)
#define OFF_MESH (OFF_IS + BB*M_PTS)

// ---------------- scratch ----------------
__device__ uint32_t g_wph[3*128*HIDN];   // W bf16-hi, k-pairs packed
__device__ uint32_t g_wpl[3*128*HIDN];   // W bf16-lo
__device__ float g_density[M_PTS];
__device__ float g_cwc[BB*HIDN];
__device__ float g_init[BB*M_PTS];
__device__ float g_bpart[BB*NTILES*TT];

__device__ __forceinline__ float fast_tanh(float x) {
    float r;
    asm("tanh.approx.f32 %0, %1;" : "=f"(r) : "f"(x));
    return r;
}

__device__ __forceinline__ float bf16lo_f(uint32_t p) {
    return __uint_as_float(p << 16);
}
__device__ __forceinline__ float bf16hi_f(uint32_t p) {
    return __uint_as_float(p & 0xffff0000u);
}
__device__ __forceinline__ uint32_t pack_split(float x0, float x1, uint32_t* lo) {
    uint32_t hp;
    asm("cvt.rn.bf16x2.f32 %0, %1, %2;" : "=r"(hp) : "f"(x1), "f"(x0));
    float h0 = bf16lo_f(hp), h1 = bf16hi_f(hp);
    uint32_t lp;
    asm("cvt.rn.bf16x2.f32 %0, %1, %2;" : "=r"(lp) : "f"(x1 - h1), "f"(x0 - h0));
    *lo = lp;
    return hp;
}

__device__ __forceinline__ void mma_bf16(float* c, const uint32_t* a, const uint32_t* b) {
    asm volatile(
        "mma.sync.aligned.m16n8k16.row.col.f32.bf16.bf16.f32 "
        "{%0,%1,%2,%3}, {%4,%5,%6,%7}, {%8,%9}, {%0,%1,%2,%3};"
        : "+f"(c[0]), "+f"(c[1]), "+f"(c[2]), "+f"(c[3])
        : "r"(a[0]), "r"(a[1]), "r"(a[2]), "r"(a[3]),
          "r"(b[0]), "r"(b[1]));
}

// ---------------- W split+pack (once) ----------------
__global__ void k_wsplitp(const float* __restrict__ Wr) {
    int i = blockIdx.x*256 + threadIdx.x;
    if (i >= 3*128*HIDN) return;
    int l  = i >> 15;
    int r2 = (i >> 8) & 127;
    int n  = i & 255;
    const float* base = Wr + l*HIDN*HIDN;
    float w0 = base[(2*r2  )*HIDN + n];
    float w1 = base[(2*r2+1)*HIDN + n];
    uint32_t lo;
    uint32_t hi = pack_split(w0, w1, &lo);
    g_wph[i] = hi;
    g_wpl[i] = lo;
}

// ===== fused density MLP: dens_in + 3 res layers (bf16 3-term) + dens_out ==
__global__ void __launch_bounds__(256) k_mlp(
    const float* __restrict__ mesh,
    const float* __restrict__ Win, const float* __restrict__ bin,
    const float* __restrict__ br,
    const float* __restrict__ Wout, const float* __restrict__ bout)
{
    extern __shared__ __align__(16) uint32_t smw[];
    uint32_t* Xh = smw + SM_XH;
    uint32_t* Xl = smw + SM_XL;
    uint32_t* Bh = smw + SM_BH;
    uint32_t* Bl = smw + SM_BL;

    int tid = threadIdx.x;
    int bm = blockIdx.x * 32;

    {
        int r  = tid >> 3;
        int c0 = (tid & 7) * 32;
        int gr = bm + r;
        bool ok = gr < M_PTS;
        float be = ok ? mesh[2*gr]   : 0.f;
        float al = ok ? mesh[2*gr+1] : 0.f;
#pragma unroll 4
        for (int p = 0; p < 16; p++) {
            int c = c0 + 2*p;
            float x0 = ok ? fmaxf(be*Win[c]   + al*Win[HIDN+c]   + bin[c],   0.f) : 0.f;
            float x1 = ok ? fmaxf(be*Win[c+1] + al*Win[HIDN+c+1] + bin[c+1], 0.f) : 0.f;
            uint32_t lo;
            uint32_t hi = pack_split(x0, x1, &lo);
            Xh[r*XP_STR + (c>>1)] = hi;
            Xl[r*XP_STR + (c>>1)] = lo;
        }
    }
    __syncthreads();

    int warp = tid >> 5, lane = tid & 31;
    int lr = lane >> 2, lc = lane & 3;
    int n_base = warp * 32;

    int woff = tid * 8;
    int wr2  = woff >> 8;
    int wcc  = woff & 255;

    for (int layer = 0; layer < 3; layer++) {
        const uint32_t* WPH = g_wph + layer*128*HIDN;
        const uint32_t* WPL = g_wpl + layer*128*HIDN;
        const float* bias = br + layer*HIDN;

        float acc[2][4][4];
#pragma unroll
        for (int t = 0; t < 2; t++)
#pragma unroll
            for (int j = 0; j < 4; j++)
#pragma unroll
                for (int q = 0; q < 4; q++) acc[t][j][q] = 0.f;

        uint4 ph0 = *(const uint4*)&WPH[woff];
        uint4 ph1 = *(const uint4*)&WPH[woff + 4];
        uint4 pl0 = *(const uint4*)&WPL[woff];
        uint4 pl1 = *(const uint4*)&WPL[woff + 4];

        for (int ch = 0; ch < 16; ch++) {
            *(uint4*)&Bh[wr2*BP_STR + wcc]     = ph0;
            *(uint4*)&Bh[wr2*BP_STR + wcc + 4] = ph1;
            *(uint4*)&Bl[wr2*BP_STR + wcc]     = pl0;
            *(uint4*)&Bl[wr2*BP_STR + wcc + 4] = pl1;
            __syncthreads();

            if (ch < 15) {
                int g = (ch + 1)*2048 + woff;
                ph0 = *(const uint4*)&WPH[g];
                ph1 = *(const uint4*)&WPH[g + 4];
                pl0 = *(const uint4*)&WPL[g];
                pl1 = *(const uint4*)&WPL[g + 4];
            }

            int k2b = ch * 8;
            uint32_t a_h[2][4], a_l[2][4];
#pragma unroll
            for (int t = 0; t < 2; t++) {
                int r = t*16 + lr;
                a_h[t][0] = Xh[ r     *XP_STR + k2b + lc];
                a_h[t][1] = Xh[(r + 8)*XP_STR + k2b + lc];
                a_h[t][2] = Xh[ r     *XP_STR + k2b + lc + 4];
                a_h[t][3] = Xh[(r + 8)*XP_STR + k2b + lc + 4];
                a_l[t][0] = Xl[ r     *XP_STR + k2b + lc];
                a_l[t][1] = Xl[(r + 8)*XP_STR + k2b + lc];
                a_l[t][2] = Xl[ r     *XP_STR + k2b + lc + 4];
                a_l[t][3] = Xl[(r + 8)*XP_STR + k2b + lc + 4];
            }
            uint32_t b_h[4][2], b_l[4][2];
#pragma unroll
            for (int j = 0; j < 4; j++) {
                int n = n_base + j*8 + lr;
                b_h[j][0] = Bh[ lc     *BP_STR + n];
                b_h[j][1] = Bh[(lc + 4)*BP_STR + n];
                b_l[j][0] = Bl[ lc     *BP_STR + n];
                b_l[j][1] = Bl[(lc + 4)*BP_STR + n];
            }
#pragma unroll
            for (int t = 0; t < 2; t++)
#pragma unroll
                for (int j = 0; j < 4; j++) {
                    mma_bf16(acc[t][j], a_h[t], b_h[j]);
                    mma_bf16(acc[t][j], a_h[t], b_l[j]);
                    mma_bf16(acc[t][j], a_l[t], b_h[j]);
                }
            __syncthreads();
        }

#pragma unroll
        for (int t = 0; t < 2; t++)
#pragma unroll
            for (int j = 0; j < 4; j++) {
                int c = n_base + j*8 + 2*lc;
                int c2 = c >> 1;
                float2 bz = *(const float2*)&bias[c];
#pragma unroll
                for (int h = 0; h < 2; h++) {
                    int r = t*16 + lr + 8*h;
                    int g = r*XP_STR + c2;
                    uint32_t hp = Xh[g], lp = Xl[g];
                    float x0 = bf16lo_f(hp) + bf16lo_f(lp);
                    float x1 = bf16hi_f(hp) + bf16hi_f(lp);
                    float y0 = x0 + fmaxf(acc[t][j][2*h]   + bz.x, 0.f);
                    float y1 = x1 + fmaxf(acc[t][j][2*h+1] + bz.y, 0.f);
                    uint32_t lo;
                    Xh[g] = pack_split(y0, y1, &lo);
                    Xl[g] = lo;
                }
            }
        __syncthreads();
    }

    {
        float b0 = bout[0];
#pragma unroll
        for (int rr = 0; rr < 4; rr++) {
            int r = warp*4 + rr;
            int gr = bm + r;
            float a = 0.f;
#pragma unroll
            for (int i = 0; i < 4; i++) {
                int c2 = lane + i*32;
                uint32_t hp = Xh[r*XP_STR + c2], lp = Xl[r*XP_STR + c2];
                a += (bf16lo_f(hp) + bf16lo_f(lp)) * Wout[2*c2];
                a += (bf16hi_f(hp) + bf16hi_f(lp)) * Wout[2*c2+1];
            }
#pragma unroll
            for (int o = 16; o; o >>= 1) a += __shfl_xor_sync(0xffffffffu, a, o);
            if (lane == 0 && gr < M_PTS)
                g_density[gr] = 1.f / (1.f + __expf(-(a + b0)));
        }
    }
}

// ---------------- encoder ctx + ctx @ Wc ----------------
__global__ void k_ctxw(const float* __restrict__ enc,
                       const float* __restrict__ mask,
                       const float* __restrict__ Ws,
                       const float* __restrict__ bs,
                       const float* __restrict__ Wc) {
    int b = blockIdx.x;
    int j = threadIdx.x;
    __shared__ float se[2*SS];
    __shared__ float sm[SS];
    __shared__ float sctx[HIDN];
    for (int i = j; i < 2*SS; i += 256) se[i] = enc[b*2*SS + i];
    for (int i = j; i < SS;   i += 256) sm[i] = mask[b*SS + i];
    __syncthreads();
    float w0 = Ws[j], w1 = Ws[HIDN + j], bj = bs[j];
    float acc = 0.f, msum = 0.f;
    for (int s = 0; s < SS; s++) {
        float mk = sm[s];
        msum += mk;
        float v = fmaxf(se[2*s]*w0 + se[2*s+1]*w1 + bj, 0.f);
        acc += mk * v;
    }
    sctx[j] = acc / fmaxf(msum, 1.f);
    __syncthreads();
    float a2 = 0.f;
    for (int k = 0; k < HIDN; k++) a2 += sctx[k] * Wc[k*HIDN + j];
    g_cwc[b*HIDN + j] = a2;
}

// ------- initial states + replication; 2 points/thread, grid 11x16 -------
__global__ void k_init(const float* __restrict__ mesh,
                       const float* __restrict__ Wm,
                       const float* __restrict__ bm,
                       const float* __restrict__ Wo,
                       const float* __restrict__ bo,
                       float* __restrict__ out) {
    int b = blockIdx.y;
    int j = threadIdx.x;
    __shared__ __align__(16) float sW0[HIDN], sW1[HIDN], sW2[HIDN], sWo[HIDN], sC[HIDN];
    sW0[j] = Wm[j];
    sW1[j] = Wm[HIDN + j];
    sW2[j] = Wm[2*HIDN + j];
    sWo[j] = Wo[j];
    sC[j]  = g_cwc[b*HIDN + j] + bm[j];
    __syncthreads();

    int m[2]; bool v[2];
    float be[2], al[2], d[2], acc[2];
#pragma unroll
    for (int q = 0; q < 2; q++) {
        m[q] = blockIdx.x*512 + q*256 + j;
        v[q] = m[q] < M_PTS;
        int mm = v[q] ? m[q] : 0;
        be[q] = mesh[2*mm];
        al[q] = mesh[2*mm + 1];
        d[q]  = g_density[mm];
        acc[q] = 0.f;
    }

    const float4* w0 = (const float4*)sW0;
    const float4* w1 = (const float4*)sW1;
    const float4* w2 = (const float4*)sW2;
    const float4* wo = (const float4*)sWo;
    const float4* cc = (const float4*)sC;
#pragma unroll 4
    for (int qq = 0; qq < HIDN/4; qq++) {
        float4 a0 = w0[qq], a1 = w1[qq], a2 = w2[qq], ao = wo[qq], ac = cc[qq];
#pragma unroll
        for (int q = 0; q < 2; q++) {
            acc[q] += fmaxf(ac.x + be[q]*a0.x + al[q]*a1.x + d[q]*a2.x, 0.f) * ao.x;
            acc[q] += fmaxf(ac.y + be[q]*a0.y + al[q]*a1.y + d[q]*a2.y, 0.f) * ao.y;
            acc[q] += fmaxf(ac.z + be[q]*a0.z + al[q]*a1.z + d[q]*a2.z, 0.f) * ao.z;
            acc[q] += fmaxf(ac.w + be[q]*a0.w + al[q]*a1.w + d[q]*a2.w, 0.f) * ao.w;
        }
    }
    float bo0 = bo[0];
#pragma unroll
    for (int q = 0; q < 2; q++) {
        if (!v[q]) continue;
        float is = tanhf(acc[q] + bo0);
        g_init[b*M_PTS + m[q]] = is;
        out[OFF_IS + (size_t)b*M_PTS + m[q]] = is;
        out[OFF_D  + (size_t)b*M_PTS + m[q]] = d[q];
        ((float2*)out)[(OFF_MESH >> 1) + (size_t)b*M_PTS + m[q]] = make_float2(be[q], al[q]);
    }
}

// ------- relay scan: 16beta x 16alpha tiles, 128 thr, 2 beta pts/thread ---
__global__ void __launch_bounds__(128) k_scan(const float* __restrict__ dec,
                                              const float* __restrict__ mesh) {
    __shared__ __align__(16) float sh_h[TT];
    __shared__ __align__(16) float tile[128*TSTR];
    __shared__ float aux[4][TC];
    int b = blockIdx.y;
    int tid = threadIdx.x;        // 0..127

    // tile_id (0..27) -> (tb, ta), ta >= tb, 7x7 upper triangle
    int tb = 0, rem = blockIdx.x;
    while (rem >= 7 - tb) { rem -= 7 - tb; tb++; }
    int ta = tb + rem;

    int ib0 = tb*TDIM + 2*(tid >> 4);
    int ib1 = ib0 + 1;
    int ia  = ta*TDIM + (tid & 15);
    bool v0 = (ib0 <= ia) && (ib0 < GRID_N) && (ia < GRID_N);
    bool v1 = (ib1 <= ia) && (ib1 < GRID_N) && (ia < GRID_N);
    int idx0 = v0 ? (ib0*GRID_N - (ib0*(ib0-1))/2 + ia - ib0) : 0;
    int idx1 = v1 ? (ib1*GRID_N - (ib1*(ib1-1))/2 + ia - ib1) : 0;

    for (int t = tid; t < TT; t += 128) sh_h[t] = dec[b*TT + t];

    float al  = v0 ? mesh[2*idx0 + 1] : (v1 ? mesh[2*idx1 + 1] : 2.f);
    float be0 = v0 ? mesh[2*idx0]     : -2.f;
    float be1 = v1 ? mesh[2*idx1]     : -2.f;
    float d0  = v0 ? g_density[idx0]  :  0.f;
    float d1  = v1 ? g_density[idx1]  :  0.f;
    float sg0 = v0 ? d0 * g_init[b*M_PTS + idx0] : 0.f;
    float sg1 = v1 ? d1 * g_init[b*M_PTS + idx1] : 0.f;
    float nd0 = -d0, nd1 = -d1;
    __syncthreads();

    float* myrow = &tile[tid*TSTR];
    int rcol  = tid & (TC-1);
    int rbase = (tid >> 5) * 32;
    float* gout = &g_bpart[((size_t)b*NTILES + blockIdx.x)*TT];

    for (int c0 = 0; c0 < TT; c0 += TC) {
#pragma unroll 2
        for (int t4 = 0; t4 < TC; t4 += 4) {
            float4 h4 = *(const float4*)&sh_h[c0 + t4];
            float o[4];
            float hts[4] = {h4.x, h4.y, h4.z, h4.w};
#pragma unroll
            for (int u = 0; u < 4; u++) {
                float ht = hts[u];
                float xu  = ht - al;
                float xd0 = be0 - ht;
                float xd1 = be1 - ht;
                bool nearany = (fabsf(xu) < CUT) | (fabsf(xd0) < CUT) | (fabsf(xd1) < CUT);
                if (__any_sync(0xffffffffu, nearany)) {
                    float wu  = 0.5f*fast_tanh(500.f*xu)  + 0.5f;
                    float wd0 = 0.5f*fast_tanh(500.f*xd0) + 0.5f;
                    float wd1 = 0.5f*fast_tanh(500.f*xd1) + 0.5f;
                    sg0 += wu  * (d0  - sg0);
                    sg1 += wu  * (d1  - sg1);
                    sg0 += wd0 * (nd0 - sg0);
                    sg1 += wd1 * (nd1 - sg1);
                } else {
                    if (xu  > 0.f) { sg0 = d0; sg1 = d1; }
                    if (xd0 > 0.f) sg0 = nd0;
                    if (xd1 > 0.f) sg1 = nd1;
                }
                o[u] = sg0 + sg1;
            }
            *(float4*)&myrow[t4] = make_float4(o[0], o[1], o[2], o[3]);
        }
        __syncthreads();
        float a = 0.f;
#pragma unroll 8
        for (int i = 0; i < 32; i++)
            a += tile[(rbase + i)*TSTR + rcol];
        aux[tid >> 5][rcol] = a;
        __syncthreads();
        if (tid < TC)
            gout[c0 + tid] = aux[0][tid] + aux[1][tid] + aux[2][tid] + aux[3][tid];
        __syncthreads();
    }
}

// ---------------- final ----------------
__global__ void k_final(const float* __restrict__ dec,
                        const float* __restrict__ hraw,
                        const float* __restrict__ mraw,
                        const float* __restrict__ oraw,
                        float* __restrict__ out) {
    __shared__ float sred[256];
    int tid = threadIdx.x;
    float a = 0.f;
    for (int i = tid; i < M_PTS; i += 256) a += g_density[i];
    sred[tid] = a;
    __syncthreads();
    for (int o = 128; o; o >>= 1) {
        if (tid < o) sred[tid] += sred[tid + o];
        __syncthreads();
    }
    float dsum = sred[0];

    int i = blockIdx.x*256 + tid;
    int b = i >> 10, t = i & 1023;
    float acc = 0.f;
#pragma unroll
    for (int k = 0; k < NTILES; k++)
        acc += g_bpart[((size_t)b*NTILES + k)*TT + t];
    float mv = acc / dsum;
    float h = dec[i];
    float hs  = 10.f / (1.f + __expf(-hraw[0]));
    float ms  = 10.f / (1.f + __expf(-mraw[0]));
    float off = -10.f + 20.f / (1.f + __expf(-oraw[0]));
    out[OFF_BOUT + i] = hs*h + ms*mv + off;
    out[OFF_M + i] = mv;
}

// ---------------- launch ----------------
extern "C" void kernel_launch(void* const* d_in, const int* in_sizes, int n_in,
                              void* d_out, int out_size) {
    (void)in_sizes; (void)n_in; (void)out_size;
    const float* enc   = (const float*)d_in[0];
    const float* dec   = (const float*)d_in[1];
    const float* msk   = (const float*)d_in[2];
    const float* mesh  = (const float*)d_in[3];
    const float* dWin  = (const float*)d_in[4];
    const float* dbin  = (const float*)d_in[5];
    const float* dWr   = (const float*)d_in[6];
    const float* dbr   = (const float*)d_in[7];
    const float* dWout = (const float*)d_in[8];
    const float* dbout = (const float*)d_in[9];
    const float* eWs   = (const float*)d_in[10];
    const float* ebs   = (const float*)d_in[11];
    const float* eWm   = (const float*)d_in[12];
    const float* eWc   = (const float*)d_in[13];
    const float* ebm   = (const float*)d_in[14];
    const float* eWo   = (const float*)d_in[15];
    const float* ebo   = (const float*)d_in[16];
    const float* hraw  = (const float*)d_in[17];
    const float* mraw  = (const float*)d_in[18];
    const float* oraw  = (const float*)d_in[19];
    float* out = (float*)d_out;

    static int smem_set = 0;
    if (!smem_set) {
        cudaFuncSetAttribute(k_mlp, cudaFuncAttributeMaxDynamicSharedMemorySize,
                             MLP_SMEM_BYTES);
        smem_set = 1;
    }

    // W split/pack + fused density MLP
    k_wsplitp<<<384, 256>>>(dWr);
    k_mlp<<<161, 256, MLP_SMEM_BYTES>>>(mesh, dWin, dbin, dbr, dWout, dbout);

    // encoder + initial states (+ density/mesh output replication)
    k_ctxw<<<BB, 256>>>(enc, msk, eWs, ebs, eWc);
    dim3 ginit(11, BB);
    k_init<<<ginit, 256>>>(mesh, eWm, ebm, eWo, ebo, out);

    // relay scan + final
    dim3 gscan(NTILES, BB);
    k_scan<<<gscan, 128>>>(dec, mesh);
    k_final<<<64, 256>>>(dec, hraw, mraw, oraw, out);
}